// round 6
// baseline (speedup 1.0000x reference)
#include <cuda_runtime.h>
#include <cuda_bf16.h>
#include <cstdint>

#define N_NODES 50000
#define N_EDGES 800000
#define F 64
#define C 16
#define N_TILES ((N_NODES + 63) / 64)              // 782

// ---------------- device scratch (device-code references ONLY) ----------
__device__ __align__(256) float g_p2[N_NODES * C];   // h1 @ Wn2
__device__ __align__(256) float g_q2[N_NODES * C];   // h1 @ Ws2
__device__ int g_src32[N_EDGES];
__device__ int g_dst32[N_EDGES];
__device__ int g_csr_src[N_EDGES];
__device__ int g_cnt[N_NODES];
__device__ int g_off[N_NODES + 1];
__device__ int g_cursor[N_NODES];
__device__ int g_is64;

// ---------------- packed f32x2 helpers ----------------
__device__ __forceinline__ unsigned long long pack2(float a, float b) {
    unsigned long long r;
    asm("mov.b64 %0, {%1, %2};" : "=l"(r) : "f"(a), "f"(b));
    return r;
}
__device__ __forceinline__ unsigned long long fma2(unsigned long long a,
                                                   unsigned long long b,
                                                   unsigned long long c) {
    unsigned long long d;
    asm("fma.rn.f32x2 %0, %1, %2, %3;" : "=l"(d) : "l"(a), "l"(b), "l"(c));
    return d;
}
__device__ __forceinline__ void unpack2(unsigned long long v, float& lo, float& hi) {
    asm("mov.b64 {%0, %1}, %2;" : "=f"(lo), "=f"(hi) : "l"(v));
}

// ---------------- detect int64-vs-int32 layout + zero counts -------------
__global__ void detect_zero_kernel(const unsigned int* __restrict__ raw_src) {
    int i = blockIdx.x * blockDim.x + threadIdx.x;
    if (i < N_NODES) g_cnt[i] = 0;
    if (blockIdx.x == 0) {
        __shared__ int any_nonzero;
        if (threadIdx.x == 0) any_nonzero = 0;
        __syncthreads();
        for (int j = threadIdx.x; j < 1024; j += blockDim.x)
            if (raw_src[2 * j + 1] != 0u) any_nonzero = 1;
        __syncthreads();
        if (threadIdx.x == 0) g_is64 = (any_nonzero == 0) ? 1 : 0;
    }
}

// convert indices + histogram dst
__global__ void convert_hist_kernel(const int* __restrict__ raw_src,
                                    const int* __restrict__ raw_dst) {
    int e = blockIdx.x * blockDim.x + threadIdx.x;
    if (e >= N_EDGES) return;
    int idx = g_is64 ? (2 * e) : e;
    int s = raw_src[idx];
    int d = raw_dst[idx];
    g_src32[e] = s;
    g_dst32[e] = d;
    atomicAdd(&g_cnt[d], 1);
}

// ---------------- single-launch exclusive scan: g_cnt -> g_off/cursor ----
// One block, 1024 threads, 49 elements each (49*1024 = 50176 >= 50000).
#define SCAN_PER 49
__global__ void scan_fused_kernel() {
    __shared__ int sh[1024];
    int t = threadIdx.x;
    int base = t * SCAN_PER;
    int sum = 0;
#pragma unroll 7
    for (int i = 0; i < SCAN_PER; i++) {
        int idx = base + i;
        if (idx < N_NODES) sum += g_cnt[idx];
    }
    sh[t] = sum;
    __syncthreads();
#pragma unroll
    for (int d = 1; d < 1024; d <<= 1) {
        int a = (t >= d) ? sh[t - d] : 0;
        __syncthreads();
        sh[t] += a;
        __syncthreads();
    }
    int run = sh[t] - sum;   // exclusive prefix of this thread's chunk
#pragma unroll 7
    for (int i = 0; i < SCAN_PER; i++) {
        int idx = base + i;
        if (idx < N_NODES) {
            int c = g_cnt[idx];
            g_off[idx] = run;
            g_cursor[idx] = run;
            run += c;
        }
    }
    if (t == 0) g_off[N_NODES] = N_EDGES;
}

__global__ void fill_kernel() {
    int e = blockIdx.x * blockDim.x + threadIdx.x;
    if (e >= N_EDGES) return;
    int d = g_dst32[e];
    int pos = atomicAdd(&g_cursor[d], 1);
    g_csr_src[pos] = g_src32[e];
}

// ---------------- fused layer1: gather + GEMM + epilogue projections ----
// Per 64-node tile:
//   A: gather mean_agg(x) -> sAT[k][node] (transposed), load x -> sXT[k][node]
//   B: h = relu(x@Ws1 + agg@Wn1 + b1)  (register-tiled, f32x2)
//   D: p2 = h@Wn2, q2 = h@Ws2 -> global
// Dyn smem: sW[128][64] | sW2[64][32] | sXT[64][68] | sAT[64][68] | sH[64][68]
#define SM_W   0
#define SM_W2  (128 * 64)
#define SM_XT  (SM_W2 + 64 * 32)
#define SM_AT  (SM_XT + 64 * 68)
#define SM_H   (SM_AT + 64 * 68)
#define SM_TOT (SM_H + 64 * 68)          // 23296 floats = 93184 B

__global__ void __launch_bounds__(256, 2)
layer1_fused_kernel(const float* __restrict__ x,
                    const float* __restrict__ Ws1,
                    const float* __restrict__ Wn1,
                    const float* __restrict__ b1,
                    const float* __restrict__ Wn2,
                    const float* __restrict__ Ws2) {
    extern __shared__ float sm[];
    int tid = threadIdx.x;

    // weights resident in smem for the whole kernel
    for (int i = tid; i < 64 * 64; i += 256) {
        int k = i >> 6, c = i & 63;
        sm[SM_W + k * 64 + c]        = Ws1[i];
        sm[SM_W + (64 + k) * 64 + c] = Wn1[i];
    }
    for (int i = tid; i < 64 * 16; i += 256) {
        int k = i >> 4, c = i & 15;
        sm[SM_W2 + k * 32 + c]      = Wn2[i];
        sm[SM_W2 + k * 32 + 16 + c] = Ws2[i];
    }
    __syncthreads();

    int ty = tid >> 4, tx = tid & 15;              // GEMM: node group / col group
    float4 bb = *(const float4*)(b1 + tx * 4);

    for (int tile = blockIdx.x; tile < N_TILES; tile += gridDim.x) {
        int node0 = tile * 64;

        // ---- phase A1: gather mean_agg into sAT (transposed [k][node]) ----
        {
            int ng = tid >> 4;          // 0..15 node-in-pass
            int l  = tid & 15;          // feature chunk (float4)
#pragma unroll
            for (int p = 0; p < 4; p++) {
                int nn = p * 16 + ng;                  // 0..63
                int node = node0 + nn;
                float4 acc = make_float4(0.f, 0.f, 0.f, 0.f);
                if (node < N_NODES) {
                    int beg = g_off[node], end = g_off[node + 1];
                    int i = beg;
                    for (; i + 4 <= end; i += 4) {
                        int s0 = g_csr_src[i];
                        int s1 = g_csr_src[i + 1];
                        int s2 = g_csr_src[i + 2];
                        int s3 = g_csr_src[i + 3];
                        float4 a = __ldg((const float4*)(x + (size_t)s0 * F + l * 4));
                        float4 b = __ldg((const float4*)(x + (size_t)s1 * F + l * 4));
                        float4 c = __ldg((const float4*)(x + (size_t)s2 * F + l * 4));
                        float4 d = __ldg((const float4*)(x + (size_t)s3 * F + l * 4));
                        acc.x += (a.x + b.x) + (c.x + d.x);
                        acc.y += (a.y + b.y) + (c.y + d.y);
                        acc.z += (a.z + b.z) + (c.z + d.z);
                        acc.w += (a.w + b.w) + (c.w + d.w);
                    }
                    for (; i < end; i++) {
                        int s0 = g_csr_src[i];
                        float4 a = __ldg((const float4*)(x + (size_t)s0 * F + l * 4));
                        acc.x += a.x; acc.y += a.y; acc.z += a.z; acc.w += a.w;
                    }
                    float inv = 1.0f / (float)max(end - beg, 1);
                    acc.x *= inv; acc.y *= inv; acc.z *= inv; acc.w *= inv;
                }
                sm[SM_AT + (l * 4 + 0) * 68 + nn] = acc.x;
                sm[SM_AT + (l * 4 + 1) * 68 + nn] = acc.y;
                sm[SM_AT + (l * 4 + 2) * 68 + nn] = acc.z;
                sm[SM_AT + (l * 4 + 3) * 68 + nn] = acc.w;
            }
        }
        // ---- phase A2: load x tile transposed into sXT [k][node] ----
        {
            int n = tid >> 2, c = tid & 3;             // 64 nodes x 4 chunks
            int node = node0 + n;
#pragma unroll
            for (int q = 0; q < 4; q++) {
                int k0 = c * 4 + q * 16;
                float4 v = make_float4(0.f, 0.f, 0.f, 0.f);
                if (node < N_NODES)
                    v = *(const float4*)(x + (size_t)node * F + k0);
                sm[SM_XT + (k0 + 0) * 68 + n] = v.x;
                sm[SM_XT + (k0 + 1) * 68 + n] = v.y;
                sm[SM_XT + (k0 + 2) * 68 + n] = v.z;
                sm[SM_XT + (k0 + 3) * 68 + n] = v.w;
            }
        }
        __syncthreads();

        // ---- phase B: register-tiled dual GEMM (f32x2) ----
        unsigned long long acc[4][2];
#pragma unroll
        for (int i = 0; i < 4; i++) { acc[i][0] = 0ull; acc[i][1] = 0ull; }
#pragma unroll 8
        for (int k = 0; k < 64; k++) {
            float4 xv = *(float4*)&sm[SM_XT + k * 68 + ty * 4];
            float4 av = *(float4*)&sm[SM_AT + k * 68 + ty * 4];
            unsigned long long wsp0, wsp1, wnp0, wnp1;
            {
                float4 ws = *(float4*)&sm[SM_W + k * 64 + tx * 4];
                float4 wn = *(float4*)&sm[SM_W + (64 + k) * 64 + tx * 4];
                wsp0 = pack2(ws.x, ws.y); wsp1 = pack2(ws.z, ws.w);
                wnp0 = pack2(wn.x, wn.y); wnp1 = pack2(wn.z, wn.w);
            }
            unsigned long long xs[4], as_[4];
            xs[0] = pack2(xv.x, xv.x); xs[1] = pack2(xv.y, xv.y);
            xs[2] = pack2(xv.z, xv.z); xs[3] = pack2(xv.w, xv.w);
            as_[0] = pack2(av.x, av.x); as_[1] = pack2(av.y, av.y);
            as_[2] = pack2(av.z, av.z); as_[3] = pack2(av.w, av.w);
#pragma unroll
            for (int i = 0; i < 4; i++) {
                acc[i][0] = fma2(wsp0, xs[i], acc[i][0]);
                acc[i][0] = fma2(wnp0, as_[i], acc[i][0]);
                acc[i][1] = fma2(wsp1, xs[i], acc[i][1]);
                acc[i][1] = fma2(wnp1, as_[i], acc[i][1]);
            }
        }
        // relu + bias -> sH [node][68]
#pragma unroll
        for (int i = 0; i < 4; i++) {
            float h0, h1, h2, h3;
            unpack2(acc[i][0], h0, h1);
            unpack2(acc[i][1], h2, h3);
            float4 hv;
            hv.x = fmaxf(h0 + bb.x, 0.f);
            hv.y = fmaxf(h1 + bb.y, 0.f);
            hv.z = fmaxf(h2 + bb.z, 0.f);
            hv.w = fmaxf(h3 + bb.w, 0.f);
            *(float4*)&sm[SM_H + (ty * 4 + i) * 68 + tx * 4] = hv;
        }
        __syncthreads();

        // ---- phase D: p2 = h@Wn2, q2 = h@Ws2 ----
        {
            int n = tid >> 2, part = tid & 3;
            unsigned long long o[4] = {0ull, 0ull, 0ull, 0ull};
#pragma unroll 8
            for (int k = 0; k < 64; k++) {
                float hv = sm[SM_H + n * 68 + k];
                unsigned long long hs = pack2(hv, hv);
                float4 w0 = *(float4*)&sm[SM_W2 + k * 32 + part * 8];
                float4 w1 = *(float4*)&sm[SM_W2 + k * 32 + part * 8 + 4];
                o[0] = fma2(pack2(w0.x, w0.y), hs, o[0]);
                o[1] = fma2(pack2(w0.z, w0.w), hs, o[1]);
                o[2] = fma2(pack2(w1.x, w1.y), hs, o[2]);
                o[3] = fma2(pack2(w1.z, w1.w), hs, o[3]);
            }
            int node = node0 + n;
            if (node < N_NODES) {
                float4 r0, r1;
                unpack2(o[0], r0.x, r0.y); unpack2(o[1], r0.z, r0.w);
                unpack2(o[2], r1.x, r1.y); unpack2(o[3], r1.z, r1.w);
                if (part < 2) {
                    *(float4*)(g_p2 + (size_t)node * C + part * 8)     = r0;
                    *(float4*)(g_p2 + (size_t)node * C + part * 8 + 4) = r1;
                } else {
                    *(float4*)(g_q2 + (size_t)node * C + (part - 2) * 8)     = r0;
                    *(float4*)(g_q2 + (size_t)node * C + (part - 2) * 8 + 4) = r1;
                }
            }
        }
        // no barrier needed before next tile's phase A: phase A writes sXT/sAT
        // which phase D never touches, and the __syncthreads() after A orders
        // them; sH is protected by the sync after B.
    }
}

// ---------------- gather2 + output: out = q2 + mean_agg(p2) + b2 --------
__global__ void gather2_out_kernel(const float* __restrict__ b2,
                                   float* __restrict__ out) {
    int node = blockIdx.x * 64 + (threadIdx.x >> 2);
    int l = threadIdx.x & 3;
    if (node >= N_NODES) return;
    int beg = g_off[node], end = g_off[node + 1];
    float4 acc = make_float4(0.f, 0.f, 0.f, 0.f);
    int i = beg;
    for (; i + 4 <= end; i += 4) {
        int s0 = g_csr_src[i];
        int s1 = g_csr_src[i + 1];
        int s2 = g_csr_src[i + 2];
        int s3 = g_csr_src[i + 3];
        float4 a = *(const float4*)(g_p2 + (size_t)s0 * C + l * 4);
        float4 b = *(const float4*)(g_p2 + (size_t)s1 * C + l * 4);
        float4 c = *(const float4*)(g_p2 + (size_t)s2 * C + l * 4);
        float4 d = *(const float4*)(g_p2 + (size_t)s3 * C + l * 4);
        acc.x += (a.x + b.x) + (c.x + d.x);
        acc.y += (a.y + b.y) + (c.y + d.y);
        acc.z += (a.z + b.z) + (c.z + d.z);
        acc.w += (a.w + b.w) + (c.w + d.w);
    }
    for (; i < end; i++) {
        int s0 = g_csr_src[i];
        float4 a = *(const float4*)(g_p2 + (size_t)s0 * C + l * 4);
        acc.x += a.x; acc.y += a.y; acc.z += a.z; acc.w += a.w;
    }
    float inv = 1.0f / (float)max(end - beg, 1);
    float4 q = *(const float4*)(g_q2 + (size_t)node * C + l * 4);
    float4 bv = *(const float4*)(b2 + l * 4);
    float4 r;
    r.x = q.x + acc.x * inv + bv.x;
    r.y = q.y + acc.y * inv + bv.y;
    r.z = q.z + acc.z * inv + bv.z;
    r.w = q.w + acc.w * inv + bv.w;
    *(float4*)(out + (size_t)node * C + l * 4) = r;
}

// ---------------- launch ----------------
extern "C" void kernel_launch(void* const* d_in, const int* in_sizes, int n_in,
                              void* d_out, int out_size) {
    const float* x   = (const float*)d_in[0];
    const int*   src = (const int*)d_in[1];
    const int*   dst = (const int*)d_in[2];
    const float* Ws1 = (const float*)d_in[3];
    const float* Wn1 = (const float*)d_in[4];
    const float* b1  = (const float*)d_in[5];
    const float* Ws2 = (const float*)d_in[6];
    const float* Wn2 = (const float*)d_in[7];
    const float* b2  = (const float*)d_in[8];
    float* out = (float*)d_out;

    // host-side attribute set; runs at capture time, not during replay
    cudaFuncSetAttribute(layer1_fused_kernel,
                         cudaFuncAttributeMaxDynamicSharedMemorySize,
                         SM_TOT * (int)sizeof(float));

    detect_zero_kernel<<<(N_NODES + 255) / 256, 256>>>((const unsigned int*)src);
    convert_hist_kernel<<<(N_EDGES + 255) / 256, 256>>>(src, dst);
    scan_fused_kernel<<<1, 1024>>>();
    fill_kernel<<<(N_EDGES + 255) / 256, 256>>>();
    layer1_fused_kernel<<<296, 256, SM_TOT * (int)sizeof(float)>>>(x, Ws1, Wn1, b1, Wn2, Ws2);
    gather2_out_kernel<<<(N_NODES + 63) / 64, 256>>>(b2, out);
}

// round 7
// speedup vs baseline: 1.0246x; 1.0246x over previous
#include <cuda_runtime.h>
#include <cuda_bf16.h>
#include <cstdint>

#define N_NODES 50000
#define N_EDGES 800000
#define F 64
#define C 16
#define N_TILES ((N_NODES + 63) / 64)              // 782

// ---------------- device scratch (device-code references ONLY) ----------
__device__ __align__(256) float g_agg1[N_NODES * F];   // mean_agg(x)
__device__ __align__(256) float g_p2  [N_NODES * C];   // h1 @ Wn2
__device__ __align__(256) float g_q2  [N_NODES * C];   // h1 @ Ws2
__device__ int g_src32[N_EDGES];
__device__ int g_dst32[N_EDGES];
__device__ int g_csr_src[N_EDGES];
__device__ int g_cnt[N_NODES];
__device__ int g_off[N_NODES + 1];
__device__ int g_cursor[N_NODES];
__device__ int g_is64;

// ---------------- packed f32x2 helpers ----------------
__device__ __forceinline__ unsigned long long pack2(float a, float b) {
    unsigned long long r;
    asm("mov.b64 %0, {%1, %2};" : "=l"(r) : "f"(a), "f"(b));
    return r;
}
__device__ __forceinline__ unsigned long long fma2(unsigned long long a,
                                                   unsigned long long b,
                                                   unsigned long long c) {
    unsigned long long d;
    asm("fma.rn.f32x2 %0, %1, %2, %3;" : "=l"(d) : "l"(a), "l"(b), "l"(c));
    return d;
}
__device__ __forceinline__ void unpack2(unsigned long long v, float& lo, float& hi) {
    asm("mov.b64 {%0, %1}, %2;" : "=f"(lo), "=f"(hi) : "l"(v));
}

// ---------------- detect int64-vs-int32 layout + zero counts -------------
__global__ void detect_zero_kernel(const unsigned int* __restrict__ raw_src) {
    int i = blockIdx.x * blockDim.x + threadIdx.x;
    if (i < N_NODES) g_cnt[i] = 0;
    if (blockIdx.x == 0) {
        __shared__ int any_nonzero;
        if (threadIdx.x == 0) any_nonzero = 0;
        __syncthreads();
        for (int j = threadIdx.x; j < 1024; j += blockDim.x)
            if (raw_src[2 * j + 1] != 0u) any_nonzero = 1;
        __syncthreads();
        if (threadIdx.x == 0) g_is64 = (any_nonzero == 0) ? 1 : 0;
    }
}

// convert indices + histogram dst
__global__ void convert_hist_kernel(const int* __restrict__ raw_src,
                                    const int* __restrict__ raw_dst) {
    int e = blockIdx.x * blockDim.x + threadIdx.x;
    if (e >= N_EDGES) return;
    int idx = g_is64 ? (2 * e) : e;
    int s = raw_src[idx];
    int d = raw_dst[idx];
    g_src32[e] = s;
    g_dst32[e] = d;
    atomicAdd(&g_cnt[d], 1);
}

// ---------------- single-launch exclusive scan: g_cnt -> g_off/cursor ----
// One block, 1024 threads, 49 elements each (49*1024 = 50176 >= 50000).
#define SCAN_PER 49
__global__ void scan_fused_kernel() {
    __shared__ int sh[1024];
    int t = threadIdx.x;
    int base = t * SCAN_PER;
    int sum = 0;
#pragma unroll 7
    for (int i = 0; i < SCAN_PER; i++) {
        int idx = base + i;
        if (idx < N_NODES) sum += g_cnt[idx];
    }
    sh[t] = sum;
    __syncthreads();
#pragma unroll
    for (int d = 1; d < 1024; d <<= 1) {
        int a = (t >= d) ? sh[t - d] : 0;
        __syncthreads();
        sh[t] += a;
        __syncthreads();
    }
    int run = sh[t] - sum;   // exclusive prefix of this thread's chunk
#pragma unroll 7
    for (int i = 0; i < SCAN_PER; i++) {
        int idx = base + i;
        if (idx < N_NODES) {
            int c = g_cnt[idx];
            g_off[idx] = run;
            g_cursor[idx] = run;
            run += c;
        }
    }
    if (t == 0) g_off[N_NODES] = N_EDGES;
}

__global__ void fill_kernel() {
    int e = blockIdx.x * blockDim.x + threadIdx.x;
    if (e >= N_EDGES) return;
    int d = g_dst32[e];
    int pos = atomicAdd(&g_cursor[d], 1);
    g_csr_src[pos] = g_src32[e];
}

// ---------------- gather1: agg1[n] = mean of x[neighbors], MLP=8 --------
// 16 lanes/node (64 floats = 16 float4), 256 thr = 16 nodes/block.
// High occupancy (small block, no smem) hides L2 latency; unroll-8 gives
// 8 independent float4 LDGs in flight per lane.
__global__ void gather1_kernel(const float* __restrict__ x) {
    int node = blockIdx.x * 16 + (threadIdx.x >> 4);
    int l = threadIdx.x & 15;
    if (node >= N_NODES) return;
    int beg = g_off[node], end = g_off[node + 1];
    float4 acc0 = make_float4(0.f, 0.f, 0.f, 0.f);
    float4 acc1 = make_float4(0.f, 0.f, 0.f, 0.f);
    int i = beg;
    for (; i + 8 <= end; i += 8) {
        int s0 = g_csr_src[i];
        int s1 = g_csr_src[i + 1];
        int s2 = g_csr_src[i + 2];
        int s3 = g_csr_src[i + 3];
        int s4 = g_csr_src[i + 4];
        int s5 = g_csr_src[i + 5];
        int s6 = g_csr_src[i + 6];
        int s7 = g_csr_src[i + 7];
        float4 a = __ldg((const float4*)(x + (size_t)s0 * F + l * 4));
        float4 b = __ldg((const float4*)(x + (size_t)s1 * F + l * 4));
        float4 c = __ldg((const float4*)(x + (size_t)s2 * F + l * 4));
        float4 d = __ldg((const float4*)(x + (size_t)s3 * F + l * 4));
        float4 e = __ldg((const float4*)(x + (size_t)s4 * F + l * 4));
        float4 f = __ldg((const float4*)(x + (size_t)s5 * F + l * 4));
        float4 g = __ldg((const float4*)(x + (size_t)s6 * F + l * 4));
        float4 h = __ldg((const float4*)(x + (size_t)s7 * F + l * 4));
        acc0.x += (a.x + b.x) + (c.x + d.x);
        acc0.y += (a.y + b.y) + (c.y + d.y);
        acc0.z += (a.z + b.z) + (c.z + d.z);
        acc0.w += (a.w + b.w) + (c.w + d.w);
        acc1.x += (e.x + f.x) + (g.x + h.x);
        acc1.y += (e.y + f.y) + (g.y + h.y);
        acc1.z += (e.z + f.z) + (g.z + h.z);
        acc1.w += (e.w + f.w) + (g.w + h.w);
    }
    for (; i + 2 <= end; i += 2) {
        int s0 = g_csr_src[i];
        int s1 = g_csr_src[i + 1];
        float4 a = __ldg((const float4*)(x + (size_t)s0 * F + l * 4));
        float4 b = __ldg((const float4*)(x + (size_t)s1 * F + l * 4));
        acc0.x += a.x + b.x; acc0.y += a.y + b.y;
        acc0.z += a.z + b.z; acc0.w += a.w + b.w;
    }
    if (i < end) {
        int s0 = g_csr_src[i];
        float4 a = __ldg((const float4*)(x + (size_t)s0 * F + l * 4));
        acc0.x += a.x; acc0.y += a.y; acc0.z += a.z; acc0.w += a.w;
    }
    float inv = 1.0f / (float)max(end - beg, 1);
    float4 r;
    r.x = (acc0.x + acc1.x) * inv;
    r.y = (acc0.y + acc1.y) * inv;
    r.z = (acc0.z + acc1.z) * inv;
    r.w = (acc0.w + acc1.w) * inv;
    *(float4*)(g_agg1 + (size_t)node * F + l * 4) = r;
}

// ---------------- layer1 (persistent, f32x2, dynamic smem) --------------
// h = relu(x@Ws1 + agg1@Wn1 + b1);  p2 = h@Wn2;  q2 = h@Ws2.
// 256 threads. Thread (ty,tx): 4 nodes x 4 cols register tile.
// Dyn smem: sW[128][64] | sW2[64][32] | sXp[16][68] | sAp[16][68] | sH[64][68]
#define SM_W   0
#define SM_W2  (128 * 64)
#define SM_XP  (SM_W2 + 64 * 32)
#define SM_AP  (SM_XP + 16 * 68)
#define SM_H   (SM_AP + 16 * 68)
#define SM_TOT (SM_H + 64 * 68)          // 16768 floats = 67072 B

__global__ void __launch_bounds__(256, 2)
layer1_kernel(const float* __restrict__ x,
              const float* __restrict__ Ws1,
              const float* __restrict__ Wn1,
              const float* __restrict__ b1,
              const float* __restrict__ Wn2,
              const float* __restrict__ Ws2) {
    extern __shared__ float sm[];
    int tid = threadIdx.x;

    // weights resident in smem for the whole kernel
    for (int i = tid; i < 64 * 64; i += 256) {
        int k = i >> 6, c = i & 63;
        sm[SM_W + k * 64 + c]        = Ws1[i];
        sm[SM_W + (64 + k) * 64 + c] = Wn1[i];
    }
    for (int i = tid; i < 64 * 16; i += 256) {
        int k = i >> 4, c = i & 15;
        sm[SM_W2 + k * 32 + c]      = Wn2[i];
        sm[SM_W2 + k * 32 + 16 + c] = Ws2[i];
    }
    __syncthreads();

    int ty = tid >> 4, tx = tid & 15;              // node group / col group
    float4 bb = *(const float4*)(b1 + tx * 4);

    for (int tile = blockIdx.x; tile < N_TILES; tile += gridDim.x) {
        int node0 = tile * 64;
        unsigned long long acc[4][2];
#pragma unroll
        for (int i = 0; i < 4; i++) { acc[i][0] = 0ull; acc[i][1] = 0ull; }

#pragma unroll
        for (int kp = 0; kp < 4; kp++) {
            __syncthreads();
            {   // load k-panel: 64 nodes x 16 k, transposed into [k][node]
                int n = tid >> 2, ch = tid & 3;
                int node = node0 + n;
                float4 vx = make_float4(0.f, 0.f, 0.f, 0.f);
                float4 va = make_float4(0.f, 0.f, 0.f, 0.f);
                if (node < N_NODES) {
                    vx = *(const float4*)(x      + (size_t)node * F + kp * 16 + ch * 4);
                    va = *(const float4*)(g_agg1 + (size_t)node * F + kp * 16 + ch * 4);
                }
                int kb = ch * 4;
                sm[SM_XP + (kb + 0) * 68 + n] = vx.x;
                sm[SM_XP + (kb + 1) * 68 + n] = vx.y;
                sm[SM_XP + (kb + 2) * 68 + n] = vx.z;
                sm[SM_XP + (kb + 3) * 68 + n] = vx.w;
                sm[SM_AP + (kb + 0) * 68 + n] = va.x;
                sm[SM_AP + (kb + 1) * 68 + n] = va.y;
                sm[SM_AP + (kb + 2) * 68 + n] = va.z;
                sm[SM_AP + (kb + 3) * 68 + n] = va.w;
            }
            __syncthreads();
#pragma unroll
            for (int k = 0; k < 16; k++) {
                float4 xv = *(float4*)&sm[SM_XP + k * 68 + ty * 4];
                float4 av = *(float4*)&sm[SM_AP + k * 68 + ty * 4];
                unsigned long long wsp0, wsp1, wnp0, wnp1;
                {
                    float4 ws = *(float4*)&sm[SM_W + (kp * 16 + k) * 64 + tx * 4];
                    float4 wn = *(float4*)&sm[SM_W + (64 + kp * 16 + k) * 64 + tx * 4];
                    wsp0 = pack2(ws.x, ws.y); wsp1 = pack2(ws.z, ws.w);
                    wnp0 = pack2(wn.x, wn.y); wnp1 = pack2(wn.z, wn.w);
                }
                unsigned long long xs[4], as_[4];
                xs[0] = pack2(xv.x, xv.x); xs[1] = pack2(xv.y, xv.y);
                xs[2] = pack2(xv.z, xv.z); xs[3] = pack2(xv.w, xv.w);
                as_[0] = pack2(av.x, av.x); as_[1] = pack2(av.y, av.y);
                as_[2] = pack2(av.z, av.z); as_[3] = pack2(av.w, av.w);
#pragma unroll
                for (int i = 0; i < 4; i++) {
                    acc[i][0] = fma2(wsp0, xs[i], acc[i][0]);
                    acc[i][0] = fma2(wnp0, as_[i], acc[i][0]);
                    acc[i][1] = fma2(wsp1, xs[i], acc[i][1]);
                    acc[i][1] = fma2(wnp1, as_[i], acc[i][1]);
                }
            }
        }
        // relu + bias -> sH
#pragma unroll
        for (int i = 0; i < 4; i++) {
            float h0, h1, h2, h3;
            unpack2(acc[i][0], h0, h1);
            unpack2(acc[i][1], h2, h3);
            float4 hv;
            hv.x = fmaxf(h0 + bb.x, 0.f);
            hv.y = fmaxf(h1 + bb.y, 0.f);
            hv.z = fmaxf(h2 + bb.z, 0.f);
            hv.w = fmaxf(h3 + bb.w, 0.f);
            *(float4*)&sm[SM_H + (ty * 4 + i) * 68 + tx * 4] = hv;
        }
        __syncthreads();
        // phase 2: p2 = h@Wn2, q2 = h@Ws2. thread: node = tid>>2, 8 of 32 cols.
        {
            int n = tid >> 2, part = tid & 3;
            unsigned long long o[4] = {0ull, 0ull, 0ull, 0ull};
#pragma unroll 8
            for (int k = 0; k < 64; k++) {
                float hv = sm[SM_H + n * 68 + k];
                unsigned long long hs = pack2(hv, hv);
                float4 w0 = *(float4*)&sm[SM_W2 + k * 32 + part * 8];
                float4 w1 = *(float4*)&sm[SM_W2 + k * 32 + part * 8 + 4];
                o[0] = fma2(pack2(w0.x, w0.y), hs, o[0]);
                o[1] = fma2(pack2(w0.z, w0.w), hs, o[1]);
                o[2] = fma2(pack2(w1.x, w1.y), hs, o[2]);
                o[3] = fma2(pack2(w1.z, w1.w), hs, o[3]);
            }
            int node = node0 + n;
            if (node < N_NODES) {
                float4 r0, r1;
                unpack2(o[0], r0.x, r0.y); unpack2(o[1], r0.z, r0.w);
                unpack2(o[2], r1.x, r1.y); unpack2(o[3], r1.z, r1.w);
                if (part < 2) {
                    *(float4*)(g_p2 + (size_t)node * C + part * 8)     = r0;
                    *(float4*)(g_p2 + (size_t)node * C + part * 8 + 4) = r1;
                } else {
                    *(float4*)(g_q2 + (size_t)node * C + (part - 2) * 8)     = r0;
                    *(float4*)(g_q2 + (size_t)node * C + (part - 2) * 8 + 4) = r1;
                }
            }
        }
        __syncthreads();
    }
}

// ---------------- gather2 + output: out = q2 + mean_agg(p2) + b2 --------
__global__ void gather2_out_kernel(const float* __restrict__ b2,
                                   float* __restrict__ out) {
    int node = blockIdx.x * 64 + (threadIdx.x >> 2);
    int l = threadIdx.x & 3;
    if (node >= N_NODES) return;
    int beg = g_off[node], end = g_off[node + 1];
    float4 acc = make_float4(0.f, 0.f, 0.f, 0.f);
    int i = beg;
    for (; i + 4 <= end; i += 4) {
        int s0 = g_csr_src[i];
        int s1 = g_csr_src[i + 1];
        int s2 = g_csr_src[i + 2];
        int s3 = g_csr_src[i + 3];
        float4 a = *(const float4*)(g_p2 + (size_t)s0 * C + l * 4);
        float4 b = *(const float4*)(g_p2 + (size_t)s1 * C + l * 4);
        float4 c = *(const float4*)(g_p2 + (size_t)s2 * C + l * 4);
        float4 d = *(const float4*)(g_p2 + (size_t)s3 * C + l * 4);
        acc.x += (a.x + b.x) + (c.x + d.x);
        acc.y += (a.y + b.y) + (c.y + d.y);
        acc.z += (a.z + b.z) + (c.z + d.z);
        acc.w += (a.w + b.w) + (c.w + d.w);
    }
    for (; i < end; i++) {
        int s0 = g_csr_src[i];
        float4 a = *(const float4*)(g_p2 + (size_t)s0 * C + l * 4);
        acc.x += a.x; acc.y += a.y; acc.z += a.z; acc.w += a.w;
    }
    float inv = 1.0f / (float)max(end - beg, 1);
    float4 q = *(const float4*)(g_q2 + (size_t)node * C + l * 4);
    float4 bv = *(const float4*)(b2 + l * 4);
    float4 r;
    r.x = q.x + acc.x * inv + bv.x;
    r.y = q.y + acc.y * inv + bv.y;
    r.z = q.z + acc.z * inv + bv.z;
    r.w = q.w + acc.w * inv + bv.w;
    *(float4*)(out + (size_t)node * C + l * 4) = r;
}

// ---------------- launch ----------------
extern "C" void kernel_launch(void* const* d_in, const int* in_sizes, int n_in,
                              void* d_out, int out_size) {
    const float* x   = (const float*)d_in[0];
    const int*   src = (const int*)d_in[1];
    const int*   dst = (const int*)d_in[2];
    const float* Ws1 = (const float*)d_in[3];
    const float* Wn1 = (const float*)d_in[4];
    const float* b1  = (const float*)d_in[5];
    const float* Ws2 = (const float*)d_in[6];
    const float* Wn2 = (const float*)d_in[7];
    const float* b2  = (const float*)d_in[8];
    float* out = (float*)d_out;

    // host-side attribute set; runs at capture time, not during replay
    cudaFuncSetAttribute(layer1_kernel,
                         cudaFuncAttributeMaxDynamicSharedMemorySize,
                         SM_TOT * (int)sizeof(float));

    detect_zero_kernel<<<(N_NODES + 255) / 256, 256>>>((const unsigned int*)src);
    convert_hist_kernel<<<(N_EDGES + 255) / 256, 256>>>(src, dst);
    scan_fused_kernel<<<1, 1024>>>();
    fill_kernel<<<(N_EDGES + 255) / 256, 256>>>();
    gather1_kernel<<<(N_NODES + 15) / 16, 256>>>(x);
    layer1_kernel<<<296, 256, SM_TOT * (int)sizeof(float)>>>(x, Ws1, Wn1, b1, Wn2, Ws2);
    gather2_out_kernel<<<(N_NODES + 63) / 64, 256>>>(b2, out);
}